// round 13
// baseline (speedup 1.0000x reference)
#include <cuda_runtime.h>
#include <cuda_fp16.h>
#include <cstddef>
#include <cstdint>

#define NNODES 100000
#define MAXE   1600000
#define SCAN_BLK 1024
#define SCAN_NB  ((NNODES + SCAN_BLK - 1) / SCAN_BLK)   // 98

// ---------------- scratch (static device globals; no allocations) ----------------
__device__ __align__(16) float  g_bufA[(size_t)NNODES * 128];
__device__ __align__(16) float  g_bufB[(size_t)NNODES * 128];
__device__ __align__(16) __half g_bufH[(size_t)NNODES * 128];
__device__ int   g_cnt[NNODES];
__device__ int   g_wp[NNODES];
__device__ int   g_row_ptr[NNODES + 1];
__device__ int   g_col[MAXE];
__device__ unsigned long long g_blkp[SCAN_NB];
__device__ float g_invdeg[NNODES];
__device__ __align__(16) float g_stats[512];   // layer1: [0,256) ; layer2: [256,512)
__device__ __align__(16) float g_ss[256];      // [scale[128], shift[128]]
__device__ int   g_is64 = 1;                   // module-init; only 0 is ever written

// ---------------- fp32 -> fp16 convert (x [N,64]) ----------------
__global__ void k_x2h(const float* __restrict__ src, __half* __restrict__ dst, int n) {
    int i = blockIdx.x * blockDim.x + threadIdx.x;           // half2 index
    int stride = gridDim.x * blockDim.x;
    const float2* s2 = (const float2*)src;
    __half2* d2 = (__half2*)dst;
    for (; i < n; i += stride) {
        float2 v = __ldg(s2 + i);
        d2[i] = __floats2half2_rn(v.x, v.y);
    }
}

// ---------------- init: zero counters/stats + dtype detect ----------------
__global__ void k_init(const unsigned int* __restrict__ w) {
    int i = blockIdx.x * blockDim.x + threadIdx.x;
    if (i < NNODES) g_cnt[i] = 0;
    if (i < 512) g_stats[i] = 0.f;
    if (i < 2048) {
        if (w[2 * i + 1] != 0u) g_is64 = 0;   // benign race: only writes 0
    }
}

__global__ void k_hist(const void* __restrict__ ei, int E) {
    int is64 = g_is64;
    int i = blockIdx.x * blockDim.x + threadIdx.x;
    int stride = gridDim.x * blockDim.x;
    if (is64) {
        const long long* p = (const long long*)ei;
        for (; i < E; i += stride) atomicAdd(&g_cnt[(int)p[i]], 1);
    } else {
        const int* p = (const int*)ei;
        for (; i < E; i += stride) atomicAdd(&g_cnt[p[i]], 1);
    }
}

// ---------------- single-kernel decoupled scan over g_cnt ----------------
__global__ void k_scan() {
    __shared__ int wsum[32];
    __shared__ int blk_off;
    int tid = threadIdx.x, lane = tid & 31, w = tid >> 5;
    int bid = blockIdx.x;
    if (tid == 0) blk_off = 0;

    int i = bid * SCAN_BLK + tid;
    int v = (i < NNODES) ? g_cnt[i] : 0;
    int s = v;
    #pragma unroll
    for (int o = 1; o < 32; o <<= 1) {
        int t = __shfl_up_sync(0xffffffffu, s, o);
        if (lane >= o) s += t;
    }
    if (lane == 31) wsum[w] = s;
    __syncthreads();
    if (w == 0) {
        int x = wsum[lane];
        int ss = x;
        #pragma unroll
        for (int o = 1; o < 32; o <<= 1) {
            int t = __shfl_up_sync(0xffffffffu, ss, o);
            if (lane >= o) ss += t;
        }
        wsum[lane] = ss - x;
        if (lane == 31) {
            atomicExch(&g_blkp[bid], (((unsigned long long)(unsigned)ss) << 1) | 1ull);
        }
    }
    __syncthreads();

    if (tid < bid) {
        const volatile unsigned long long* p = &g_blkp[tid];
        unsigned long long pv;
        do { pv = *p; } while (!(pv & 1ull));
        atomicAdd(&blk_off, (int)(pv >> 1));
    }
    __syncthreads();

    int incl = s + wsum[w] + blk_off;
    if (i < NNODES) {
        g_row_ptr[i + 1] = incl;
        g_wp[i] = incl - v;
        g_invdeg[i] = 1.0f / ((float)v + 1e-6f);
        if (i == 0) g_row_ptr[0] = 0;
    }
}

__global__ void k_fill(const void* __restrict__ ei, int E) {
    int is64 = g_is64;
    int i = blockIdx.x * blockDim.x + threadIdx.x;
    int stride = gridDim.x * blockDim.x;
    if (is64) {
        const long long* p = (const long long*)ei;
        for (; i < E; i += stride) {
            int r = (int)p[i];
            int c = (int)p[E + i];
            int q = atomicAdd(&g_wp[r], 1);
            g_col[q] = c;
        }
    } else {
        const int* p = (const int*)ei;
        for (; i < E; i += stride) {
            int r = p[i];
            int c = p[E + i];
            int q = atomicAdd(&g_wp[r], 1);
            g_col[q] = c;
        }
    }
}

// ---------------- aggregation kernels (warp per node, fp16 gather) ------
__global__ void k_agg64h(const __half* __restrict__ src, float* __restrict__ dst) {
    int gw = (blockIdx.x * blockDim.x + threadIdx.x) >> 5;
    if (gw >= NNODES) return;
    int lane = threadIdx.x & 31;
    int beg = g_row_ptr[gw], end = g_row_ptr[gw + 1];
    float2 a0 = {0.f, 0.f}, a1 = {0.f, 0.f};
    const __half2* s2 = (const __half2*)src;
    int e = beg;
    for (; e + 3 < end; e += 4) {
        int c0 = __ldg(&g_col[e]),     c1 = __ldg(&g_col[e + 1]);
        int c2 = __ldg(&g_col[e + 2]), c3 = __ldg(&g_col[e + 3]);
        float2 v0 = __half22float2(__ldg(s2 + (size_t)c0 * 32 + lane));
        float2 v1 = __half22float2(__ldg(s2 + (size_t)c1 * 32 + lane));
        float2 v2 = __half22float2(__ldg(s2 + (size_t)c2 * 32 + lane));
        float2 v3 = __half22float2(__ldg(s2 + (size_t)c3 * 32 + lane));
        a0.x += v0.x; a0.y += v0.y;
        a1.x += v1.x; a1.y += v1.y;
        a0.x += v2.x; a0.y += v2.y;
        a1.x += v3.x; a1.y += v3.y;
    }
    for (; e < end; e++) {
        int c0 = __ldg(&g_col[e]);
        float2 v0 = __half22float2(__ldg(s2 + (size_t)c0 * 32 + lane));
        a0.x += v0.x; a0.y += v0.y;
    }
    float w = g_invdeg[gw];
    float2 r;
    r.x = (a0.x + a1.x) * w;
    r.y = (a0.y + a1.y) * w;
    ((float2*)dst)[(size_t)gw * 32 + lane] = r;
}

// 128-dim fp16 gather + BN(scale/shift)+relu on the fly, 4-edge unroll
__global__ void k_agg128h_bn(const __half* __restrict__ src, float* __restrict__ dst) {
    int gw = (blockIdx.x * blockDim.x + threadIdx.x) >> 5;
    if (gw >= NNODES) return;
    int lane = threadIdx.x & 31;
    float4 sc = *(const float4*)&g_ss[lane * 4];
    float4 sh = *(const float4*)&g_ss[128 + lane * 4];
    int beg = g_row_ptr[gw], end = g_row_ptr[gw + 1];
    float4 a0 = {0.f, 0.f, 0.f, 0.f}, a1 = {0.f, 0.f, 0.f, 0.f};
    const uint2* s8 = (const uint2*)src;   // 4 halves per lane, row = 32 uint2
    int e = beg;
    for (; e + 3 < end; e += 4) {
        int c0 = __ldg(&g_col[e]),     c1 = __ldg(&g_col[e + 1]);
        int c2 = __ldg(&g_col[e + 2]), c3 = __ldg(&g_col[e + 3]);
        uint2 u0 = __ldg(s8 + (size_t)c0 * 32 + lane);
        uint2 u1 = __ldg(s8 + (size_t)c1 * 32 + lane);
        uint2 u2 = __ldg(s8 + (size_t)c2 * 32 + lane);
        uint2 u3 = __ldg(s8 + (size_t)c3 * 32 + lane);
        float2 p00 = __half22float2(*(__half2*)&u0.x);
        float2 p01 = __half22float2(*(__half2*)&u0.y);
        float2 p10 = __half22float2(*(__half2*)&u1.x);
        float2 p11 = __half22float2(*(__half2*)&u1.y);
        float2 p20 = __half22float2(*(__half2*)&u2.x);
        float2 p21 = __half22float2(*(__half2*)&u2.y);
        float2 p30 = __half22float2(*(__half2*)&u3.x);
        float2 p31 = __half22float2(*(__half2*)&u3.y);
        a0.x += fmaxf(fmaf(p00.x, sc.x, sh.x), 0.f);
        a0.y += fmaxf(fmaf(p00.y, sc.y, sh.y), 0.f);
        a0.z += fmaxf(fmaf(p01.x, sc.z, sh.z), 0.f);
        a0.w += fmaxf(fmaf(p01.y, sc.w, sh.w), 0.f);
        a1.x += fmaxf(fmaf(p10.x, sc.x, sh.x), 0.f);
        a1.y += fmaxf(fmaf(p10.y, sc.y, sh.y), 0.f);
        a1.z += fmaxf(fmaf(p11.x, sc.z, sh.z), 0.f);
        a1.w += fmaxf(fmaf(p11.y, sc.w, sh.w), 0.f);
        a0.x += fmaxf(fmaf(p20.x, sc.x, sh.x), 0.f);
        a0.y += fmaxf(fmaf(p20.y, sc.y, sh.y), 0.f);
        a0.z += fmaxf(fmaf(p21.x, sc.z, sh.z), 0.f);
        a0.w += fmaxf(fmaf(p21.y, sc.w, sh.w), 0.f);
        a1.x += fmaxf(fmaf(p30.x, sc.x, sh.x), 0.f);
        a1.y += fmaxf(fmaf(p30.y, sc.y, sh.y), 0.f);
        a1.z += fmaxf(fmaf(p31.x, sc.z, sh.z), 0.f);
        a1.w += fmaxf(fmaf(p31.y, sc.w, sh.w), 0.f);
    }
    for (; e < end; e++) {
        int c0 = __ldg(&g_col[e]);
        uint2 u0 = __ldg(s8 + (size_t)c0 * 32 + lane);
        float2 p00 = __half22float2(*(__half2*)&u0.x);
        float2 p01 = __half22float2(*(__half2*)&u0.y);
        a0.x += fmaxf(fmaf(p00.x, sc.x, sh.x), 0.f);
        a0.y += fmaxf(fmaf(p00.y, sc.y, sh.y), 0.f);
        a0.z += fmaxf(fmaf(p01.x, sc.z, sh.z), 0.f);
        a0.w += fmaxf(fmaf(p01.y, sc.w, sh.w), 0.f);
    }
    float w = g_invdeg[gw];
    float4 r;
    r.x = (a0.x + a1.x) * w;
    r.y = (a0.y + a1.y) * w;
    r.z = (a0.z + a1.z) * w;
    r.w = (a0.w + a1.w) * w;
    ((float4*)dst)[(size_t)gw * 32 + lane] = r;
}

// final: fp16 gather of t [N,64], add bias b3 -> d_out (fp32)
__global__ void k_agg64h_bias(const __half* __restrict__ src,
                              const float* __restrict__ b3,
                              float* __restrict__ dst) {
    int gw = (blockIdx.x * blockDim.x + threadIdx.x) >> 5;
    if (gw >= NNODES) return;
    int lane = threadIdx.x & 31;
    float2 bb = __ldg((const float2*)b3 + lane);
    int beg = g_row_ptr[gw], end = g_row_ptr[gw + 1];
    float2 a0 = {0.f, 0.f}, a1 = {0.f, 0.f};
    const __half2* s2 = (const __half2*)src;
    int e = beg;
    for (; e + 3 < end; e += 4) {
        int c0 = __ldg(&g_col[e]),     c1 = __ldg(&g_col[e + 1]);
        int c2 = __ldg(&g_col[e + 2]), c3 = __ldg(&g_col[e + 3]);
        float2 v0 = __half22float2(__ldg(s2 + (size_t)c0 * 32 + lane));
        float2 v1 = __half22float2(__ldg(s2 + (size_t)c1 * 32 + lane));
        float2 v2 = __half22float2(__ldg(s2 + (size_t)c2 * 32 + lane));
        float2 v3 = __half22float2(__ldg(s2 + (size_t)c3 * 32 + lane));
        a0.x += v0.x; a0.y += v0.y;
        a1.x += v1.x; a1.y += v1.y;
        a0.x += v2.x; a0.y += v2.y;
        a1.x += v3.x; a1.y += v3.y;
    }
    for (; e < end; e++) {
        int c0 = __ldg(&g_col[e]);
        float2 v0 = __half22float2(__ldg(s2 + (size_t)c0 * 32 + lane));
        a0.x += v0.x; a0.y += v0.y;
    }
    float w = g_invdeg[gw];
    float2 r;
    r.x = fmaf(a0.x + a1.x, w, bb.x);
    r.y = fmaf(a0.y + a1.y, w, bb.y);
    ((float2*)dst)[(size_t)gw * 32 + lane] = r;
}

// ---------------- GEMM (FFMA, BM=64/TM=4, KC=16, register-prefetch) ------------
// out[n][m] = sum_k A[n][k]*W[m][k] (+bias); opt BN+relu on A; opt col stats;
// opt fp16 output. Smaller per-thread tile -> ~3 CTAs/SM for latency hiding.
template <int KD, int MD, int TN, bool BN_IN, bool STATS, bool BIAS, bool HOUT, int SOFF>
__global__ void __launch_bounds__(256, 3)
k_gemm(const float* __restrict__ A, const float* __restrict__ W,
       const float* __restrict__ bias, void* __restrict__ out, int nrows) {
    constexpr int KC = 16, BM = 64, TM = 4;
    constexpr int NCH = KD / KC;
    constexpr int AIT = BM * KC / 256;   // 4
    constexpr int WIT = MD * KC / 256;   // 8 (MD=128) or 4 (MD=64)
    __shared__ __align__(16) float As[KC][BM + 4];
    __shared__ __align__(16) float Ws[KC][MD];
    __shared__ float s_sum[128];
    __shared__ float s_sq[128];

    int tid = threadIdx.x;
    int tr = tid >> 4, tc = tid & 15;
    int row0 = blockIdx.x * BM;

    float acc[TM][TN];
    #pragma unroll
    for (int i = 0; i < TM; i++)
        #pragma unroll
        for (int j = 0; j < TN; j++) acc[i][j] = 0.f;

    if (STATS && tid < MD) { s_sum[tid] = 0.f; s_sq[tid] = 0.f; }

    float pa[AIT], pw[WIT];
    // prefetch chunk 0
    #pragma unroll
    for (int it = 0; it < AIT; it++) {
        int idx = tid + it * 256;
        int k = idx & (KC - 1), r = idx >> 4;
        int gr = row0 + r;
        pa[it] = (gr < nrows) ? __ldg(&A[(size_t)gr * KD + k]) : 0.f;
    }
    #pragma unroll
    for (int it = 0; it < WIT; it++) {
        int idx = tid + it * 256;
        int k = idx & (KC - 1), c = idx >> 4;
        pw[it] = __ldg(&W[(size_t)c * KD + k]);
    }

    for (int cc = 0; cc < NCH; cc++) {
        __syncthreads();   // previous chunk's compute done -> safe to overwrite smem
        #pragma unroll
        for (int it = 0; it < AIT; it++) {
            int idx = tid + it * 256;
            int k = idx & (KC - 1), r = idx >> 4;
            float v = pa[it];
            if (BN_IN) {
                v = fmaxf(fmaf(v, __ldg(&g_ss[cc * KC + k]),
                               __ldg(&g_ss[128 + cc * KC + k])), 0.f);
            }
            As[k][r] = v;
        }
        #pragma unroll
        for (int it = 0; it < WIT; it++) {
            int idx = tid + it * 256;
            int k = idx & (KC - 1), c = idx >> 4;
            Ws[k][c] = pw[it];
        }
        __syncthreads();

        if (cc + 1 < NCH) {
            int kc = (cc + 1) * KC;
            #pragma unroll
            for (int it = 0; it < AIT; it++) {
                int idx = tid + it * 256;
                int k = idx & (KC - 1), r = idx >> 4;
                int gr = row0 + r;
                pa[it] = (gr < nrows) ? __ldg(&A[(size_t)gr * KD + kc + k]) : 0.f;
            }
            #pragma unroll
            for (int it = 0; it < WIT; it++) {
                int idx = tid + it * 256;
                int k = idx & (KC - 1), c = idx >> 4;
                pw[it] = __ldg(&W[(size_t)c * KD + kc + k]);
            }
        }

        #pragma unroll
        for (int k = 0; k < KC; k++) {
            float4 av = *(const float4*)&As[k][tr * TM];
            float a[TM] = {av.x, av.y, av.z, av.w};
            float wv[TN];
            float4 w0 = *(const float4*)&Ws[k][tc * 4];
            wv[0] = w0.x; wv[1] = w0.y; wv[2] = w0.z; wv[3] = w0.w;
            if (TN == 8) {
                float4 w1 = *(const float4*)&Ws[k][64 + tc * 4];
                wv[4] = w1.x; wv[5] = w1.y; wv[6] = w1.z; wv[7] = w1.w;
            }
            #pragma unroll
            for (int i = 0; i < TM; i++)
                #pragma unroll
                for (int j = 0; j < TN; j++)
                    acc[i][j] = fmaf(a[i], wv[j], acc[i][j]);
        }
    }

    float bj[TN];
    #pragma unroll
    for (int j = 0; j < TN; j++) {
        int c = (TN == 8) ? ((j < 4) ? tc * 4 + j : 64 + tc * 4 + (j - 4)) : tc * 4 + j;
        bj[j] = BIAS ? __ldg(&bias[c]) : 0.f;
    }

    float csum[TN], csq[TN];
    #pragma unroll
    for (int j = 0; j < TN; j++) { csum[j] = 0.f; csq[j] = 0.f; }

    #pragma unroll
    for (int i = 0; i < TM; i++) {
        int gr = row0 + tr * TM + i;
        if (gr < nrows) {
            float h[TN];
            #pragma unroll
            for (int j = 0; j < TN; j++) h[j] = acc[i][j] + bj[j];
            if (HOUT) {
                __half* oh = (__half*)out;
                __half2 p0 = __floats2half2_rn(h[0], h[1]);
                __half2 p1 = __floats2half2_rn(h[2], h[3]);
                uint2 pk;
                pk.x = *(uint32_t*)&p0; pk.y = *(uint32_t*)&p1;
                *(uint2*)&oh[(size_t)gr * MD + tc * 4] = pk;
                if (TN == 8) {
                    __half2 p2 = __floats2half2_rn(h[4], h[5]);
                    __half2 p3 = __floats2half2_rn(h[6], h[7]);
                    uint2 pk2;
                    pk2.x = *(uint32_t*)&p2; pk2.y = *(uint32_t*)&p3;
                    *(uint2*)&oh[(size_t)gr * MD + 64 + tc * 4] = pk2;
                }
            } else {
                float* of = (float*)out;
                float4 o0 = {h[0], h[1], h[2], h[3]};
                *(float4*)&of[(size_t)gr * MD + tc * 4] = o0;
                if (TN == 8) {
                    float4 o1 = {h[4], h[5], h[6], h[7]};
                    *(float4*)&of[(size_t)gr * MD + 64 + tc * 4] = o1;
                }
            }
            if (STATS) {
                #pragma unroll
                for (int j = 0; j < TN; j++) { csum[j] += h[j]; csq[j] += h[j] * h[j]; }
            }
        }
    }

    if (STATS) {
        #pragma unroll
        for (int j = 0; j < TN; j++) {
            int c = (TN == 8) ? ((j < 4) ? tc * 4 + j : 64 + tc * 4 + (j - 4)) : tc * 4 + j;
            atomicAdd(&s_sum[c], csum[j]);
            atomicAdd(&s_sq[c], csq[j]);
        }
        __syncthreads();
        if (tid < MD) {
            atomicAdd(&g_stats[SOFF + tid], s_sum[tid]);
            atomicAdd(&g_stats[SOFF + 128 + tid], s_sq[tid]);
        }
    }
}

__global__ void k_bnfin(const float* __restrict__ gamma,
                        const float* __restrict__ beta, int soff) {
    int c = threadIdx.x;
    if (c < 128) {
        float s = g_stats[soff + c], q = g_stats[soff + 128 + c];
        float mean = s * (1.0f / NNODES);
        float var = q * (1.0f / NNODES) - mean * mean;
        float sc = __ldg(&gamma[c]) * rsqrtf(var + 1e-5f);
        g_ss[c] = sc;
        g_ss[128 + c] = fmaf(-mean, sc, __ldg(&beta[c]));
    }
}

// ---------------- launch ----------------
extern "C" void kernel_launch(void* const* d_in, const int* in_sizes, int n_in,
                              void* d_out, int out_size) {
    const float* x   = (const float*)d_in[0];
    const void*  ei  = d_in[1];
    const float* W1  = (const float*)d_in[2];
    const float* b1  = (const float*)d_in[3];
    const float* ga1 = (const float*)d_in[4];
    const float* be1 = (const float*)d_in[5];
    const float* W2  = (const float*)d_in[6];
    const float* b2  = (const float*)d_in[7];
    const float* ga2 = (const float*)d_in[8];
    const float* be2 = (const float*)d_in[9];
    const float* W3  = (const float*)d_in[10];
    const float* b3  = (const float*)d_in[11];
    float* out = (float*)d_out;

    int E = in_sizes[1] / 2;
    if (E > MAXE) E = MAXE;

    float  *bufA, *bufB;
    __half *bufH;
    cudaGetSymbolAddress((void**)&bufA, g_bufA);
    cudaGetSymbolAddress((void**)&bufB, g_bufB);
    cudaGetSymbolAddress((void**)&bufH, g_bufH);

    // frontend
    k_x2h<<<512, 256>>>(x, bufH, NNODES * 32);
    k_init<<<SCAN_NB, SCAN_BLK>>>((const unsigned int*)ei);
    k_hist<<<1024, 256>>>(ei, E);
    k_scan<<<SCAN_NB, SCAN_BLK>>>();
    k_fill<<<1024, 256>>>(ei, E);

    const int aggBlocks = (NNODES * 32 + 255) / 256;
    const int gemmBlocks = (NNODES + 63) / 64;

    // layer 1: agg(x fp16) -> bufA[N,64]; GEMM1 (+b1, stats) -> bufH[N,128] fp16
    k_agg64h<<<aggBlocks, 256>>>(bufH, bufA);
    k_gemm<64, 128, 8, false, true, true, true, 0><<<gemmBlocks, 256>>>(bufA, W1, b1, bufH, NNODES);
    k_bnfin<<<1, 128>>>(ga1, be1, 0);

    // layer 2: agg(relu(BN1(h1))) from fp16 -> bufA[N,128]; GEMM2 -> bufB[N,128] fp32
    k_agg128h_bn<<<aggBlocks, 256>>>(bufH, bufA);
    k_gemm<128, 128, 8, false, true, true, false, 256><<<gemmBlocks, 256>>>(bufA, W2, b2, bufB, NNODES);
    k_bnfin<<<1, 128>>>(ga2, be2, 256);

    // layer 3: t = relu(BN2(h2)) @ W3^T -> bufH[N,64] fp16; agg(t)+b3 -> out
    k_gemm<128, 64, 4, true, false, false, true, 0><<<gemmBlocks, 256>>>(bufB, W3, nullptr, bufH, NNODES);
    k_agg64h_bias<<<aggBlocks, 256>>>(bufH, b3, out);
}

// round 14
// speedup vs baseline: 1.1067x; 1.1067x over previous
#include <cuda_runtime.h>
#include <cuda_fp16.h>
#include <cstddef>
#include <cstdint>

#define NNODES 100000
#define MAXE   1600000
#define SCAN_BLK 1024
#define SCAN_NB  ((NNODES + SCAN_BLK - 1) / SCAN_BLK)   // 98

// ---------------- scratch (static device globals; no allocations) ----------------
__device__ __align__(16) float  g_bufA[(size_t)NNODES * 128];
__device__ __align__(16) float  g_bufB[(size_t)NNODES * 128];
__device__ __align__(16) __half g_bufH[(size_t)NNODES * 128];
__device__ int   g_cnt[NNODES];
__device__ int   g_wp[NNODES];
__device__ int   g_row_ptr[NNODES + 1];
__device__ int   g_col[MAXE];
__device__ unsigned long long g_blkp[SCAN_NB];
__device__ float g_invdeg[NNODES];
__device__ __align__(16) float g_stats[512];   // layer1: [0,256) ; layer2: [256,512)
__device__ __align__(16) float g_ss[256];      // [scale[128], shift[128]]
__device__ unsigned g_done[2];                 // GEMM last-block counters
__device__ int   g_is64 = 1;                   // module-init; only 0 is ever written

// ---------------- fp32 -> fp16 convert (x [N,64]) ----------------
__global__ void k_x2h(const float* __restrict__ src, __half* __restrict__ dst, int n) {
    int i = blockIdx.x * blockDim.x + threadIdx.x;           // half2 index
    int stride = gridDim.x * blockDim.x;
    const float2* s2 = (const float2*)src;
    __half2* d2 = (__half2*)dst;
    for (; i < n; i += stride) {
        float2 v = __ldg(s2 + i);
        d2[i] = __floats2half2_rn(v.x, v.y);
    }
}

// ---------------- init: zero counters/stats + dtype detect ----------------
__global__ void k_init(const unsigned int* __restrict__ w) {
    int i = blockIdx.x * blockDim.x + threadIdx.x;
    if (i < NNODES) g_cnt[i] = 0;
    if (i < 512) g_stats[i] = 0.f;
    if (i < 2) g_done[i] = 0u;
    if (i < 2048) {
        if (w[2 * i + 1] != 0u) g_is64 = 0;   // benign race: only writes 0
    }
}

__global__ void k_hist(const void* __restrict__ ei, int E) {
    int is64 = g_is64;
    int i = blockIdx.x * blockDim.x + threadIdx.x;
    int stride = gridDim.x * blockDim.x;
    if (is64) {
        const long long* p = (const long long*)ei;
        for (; i < E; i += stride) atomicAdd(&g_cnt[(int)p[i]], 1);
    } else {
        const int* p = (const int*)ei;
        for (; i < E; i += stride) atomicAdd(&g_cnt[p[i]], 1);
    }
}

// ---------------- single-kernel decoupled scan over g_cnt ----------------
__global__ void k_scan() {
    __shared__ int wsum[32];
    __shared__ int blk_off;
    int tid = threadIdx.x, lane = tid & 31, w = tid >> 5;
    int bid = blockIdx.x;
    if (tid == 0) blk_off = 0;

    int i = bid * SCAN_BLK + tid;
    int v = (i < NNODES) ? g_cnt[i] : 0;
    int s = v;
    #pragma unroll
    for (int o = 1; o < 32; o <<= 1) {
        int t = __shfl_up_sync(0xffffffffu, s, o);
        if (lane >= o) s += t;
    }
    if (lane == 31) wsum[w] = s;
    __syncthreads();
    if (w == 0) {
        int x = wsum[lane];
        int ss = x;
        #pragma unroll
        for (int o = 1; o < 32; o <<= 1) {
            int t = __shfl_up_sync(0xffffffffu, ss, o);
            if (lane >= o) ss += t;
        }
        wsum[lane] = ss - x;
        if (lane == 31) {
            atomicExch(&g_blkp[bid], (((unsigned long long)(unsigned)ss) << 1) | 1ull);
        }
    }
    __syncthreads();

    if (tid < bid) {
        const volatile unsigned long long* p = &g_blkp[tid];
        unsigned long long pv;
        do { pv = *p; } while (!(pv & 1ull));
        atomicAdd(&blk_off, (int)(pv >> 1));
    }
    __syncthreads();

    int incl = s + wsum[w] + blk_off;
    if (i < NNODES) {
        g_row_ptr[i + 1] = incl;
        g_wp[i] = incl - v;
        g_invdeg[i] = 1.0f / ((float)v + 1e-6f);
        if (i == 0) g_row_ptr[0] = 0;
    }
}

__global__ void k_fill(const void* __restrict__ ei, int E) {
    int is64 = g_is64;
    int i = blockIdx.x * blockDim.x + threadIdx.x;
    int stride = gridDim.x * blockDim.x;
    if (is64) {
        const long long* p = (const long long*)ei;
        for (; i < E; i += stride) {
            int r = (int)p[i];
            int c = (int)p[E + i];
            int q = atomicAdd(&g_wp[r], 1);
            g_col[q] = c;
        }
    } else {
        const int* p = (const int*)ei;
        for (; i < E; i += stride) {
            int r = p[i];
            int c = p[E + i];
            int q = atomicAdd(&g_wp[r], 1);
            g_col[q] = c;
        }
    }
}

// ---------------- aggregation kernels (warp per node, fp16 gather) ------
__global__ void k_agg64h(const __half* __restrict__ src, float* __restrict__ dst) {
    int gw = (blockIdx.x * blockDim.x + threadIdx.x) >> 5;
    if (gw >= NNODES) return;
    int lane = threadIdx.x & 31;
    int beg = g_row_ptr[gw], end = g_row_ptr[gw + 1];
    float2 a0 = {0.f, 0.f}, a1 = {0.f, 0.f};
    const __half2* s2 = (const __half2*)src;
    int e = beg;
    for (; e + 3 < end; e += 4) {
        int c0 = __ldg(&g_col[e]),     c1 = __ldg(&g_col[e + 1]);
        int c2 = __ldg(&g_col[e + 2]), c3 = __ldg(&g_col[e + 3]);
        float2 v0 = __half22float2(__ldg(s2 + (size_t)c0 * 32 + lane));
        float2 v1 = __half22float2(__ldg(s2 + (size_t)c1 * 32 + lane));
        float2 v2 = __half22float2(__ldg(s2 + (size_t)c2 * 32 + lane));
        float2 v3 = __half22float2(__ldg(s2 + (size_t)c3 * 32 + lane));
        a0.x += v0.x; a0.y += v0.y;
        a1.x += v1.x; a1.y += v1.y;
        a0.x += v2.x; a0.y += v2.y;
        a1.x += v3.x; a1.y += v3.y;
    }
    for (; e < end; e++) {
        int c0 = __ldg(&g_col[e]);
        float2 v0 = __half22float2(__ldg(s2 + (size_t)c0 * 32 + lane));
        a0.x += v0.x; a0.y += v0.y;
    }
    float w = g_invdeg[gw];
    float2 r;
    r.x = (a0.x + a1.x) * w;
    r.y = (a0.y + a1.y) * w;
    ((float2*)dst)[(size_t)gw * 32 + lane] = r;
}

// 128-dim fp16 gather + BN(scale/shift)+relu on the fly, 4-edge unroll
__global__ void k_agg128h_bn(const __half* __restrict__ src, float* __restrict__ dst) {
    int gw = (blockIdx.x * blockDim.x + threadIdx.x) >> 5;
    if (gw >= NNODES) return;
    int lane = threadIdx.x & 31;
    float4 sc = *(const float4*)&g_ss[lane * 4];
    float4 sh = *(const float4*)&g_ss[128 + lane * 4];
    int beg = g_row_ptr[gw], end = g_row_ptr[gw + 1];
    float4 a0 = {0.f, 0.f, 0.f, 0.f}, a1 = {0.f, 0.f, 0.f, 0.f};
    const uint2* s8 = (const uint2*)src;   // 4 halves per lane, row = 32 uint2
    int e = beg;
    for (; e + 3 < end; e += 4) {
        int c0 = __ldg(&g_col[e]),     c1 = __ldg(&g_col[e + 1]);
        int c2 = __ldg(&g_col[e + 2]), c3 = __ldg(&g_col[e + 3]);
        uint2 u0 = __ldg(s8 + (size_t)c0 * 32 + lane);
        uint2 u1 = __ldg(s8 + (size_t)c1 * 32 + lane);
        uint2 u2 = __ldg(s8 + (size_t)c2 * 32 + lane);
        uint2 u3 = __ldg(s8 + (size_t)c3 * 32 + lane);
        float2 p00 = __half22float2(*(__half2*)&u0.x);
        float2 p01 = __half22float2(*(__half2*)&u0.y);
        float2 p10 = __half22float2(*(__half2*)&u1.x);
        float2 p11 = __half22float2(*(__half2*)&u1.y);
        float2 p20 = __half22float2(*(__half2*)&u2.x);
        float2 p21 = __half22float2(*(__half2*)&u2.y);
        float2 p30 = __half22float2(*(__half2*)&u3.x);
        float2 p31 = __half22float2(*(__half2*)&u3.y);
        a0.x += fmaxf(fmaf(p00.x, sc.x, sh.x), 0.f);
        a0.y += fmaxf(fmaf(p00.y, sc.y, sh.y), 0.f);
        a0.z += fmaxf(fmaf(p01.x, sc.z, sh.z), 0.f);
        a0.w += fmaxf(fmaf(p01.y, sc.w, sh.w), 0.f);
        a1.x += fmaxf(fmaf(p10.x, sc.x, sh.x), 0.f);
        a1.y += fmaxf(fmaf(p10.y, sc.y, sh.y), 0.f);
        a1.z += fmaxf(fmaf(p11.x, sc.z, sh.z), 0.f);
        a1.w += fmaxf(fmaf(p11.y, sc.w, sh.w), 0.f);
        a0.x += fmaxf(fmaf(p20.x, sc.x, sh.x), 0.f);
        a0.y += fmaxf(fmaf(p20.y, sc.y, sh.y), 0.f);
        a0.z += fmaxf(fmaf(p21.x, sc.z, sh.z), 0.f);
        a0.w += fmaxf(fmaf(p21.y, sc.w, sh.w), 0.f);
        a1.x += fmaxf(fmaf(p30.x, sc.x, sh.x), 0.f);
        a1.y += fmaxf(fmaf(p30.y, sc.y, sh.y), 0.f);
        a1.z += fmaxf(fmaf(p31.x, sc.z, sh.z), 0.f);
        a1.w += fmaxf(fmaf(p31.y, sc.w, sh.w), 0.f);
    }
    for (; e < end; e++) {
        int c0 = __ldg(&g_col[e]);
        uint2 u0 = __ldg(s8 + (size_t)c0 * 32 + lane);
        float2 p00 = __half22float2(*(__half2*)&u0.x);
        float2 p01 = __half22float2(*(__half2*)&u0.y);
        a0.x += fmaxf(fmaf(p00.x, sc.x, sh.x), 0.f);
        a0.y += fmaxf(fmaf(p00.y, sc.y, sh.y), 0.f);
        a0.z += fmaxf(fmaf(p01.x, sc.z, sh.z), 0.f);
        a0.w += fmaxf(fmaf(p01.y, sc.w, sh.w), 0.f);
    }
    float w = g_invdeg[gw];
    float4 r;
    r.x = (a0.x + a1.x) * w;
    r.y = (a0.y + a1.y) * w;
    r.z = (a0.z + a1.z) * w;
    r.w = (a0.w + a1.w) * w;
    ((float4*)dst)[(size_t)gw * 32 + lane] = r;
}

// final: fp16 gather of t [N,64], add bias b3 -> d_out (fp32)
__global__ void k_agg64h_bias(const __half* __restrict__ src,
                              const float* __restrict__ b3,
                              float* __restrict__ dst) {
    int gw = (blockIdx.x * blockDim.x + threadIdx.x) >> 5;
    if (gw >= NNODES) return;
    int lane = threadIdx.x & 31;
    float2 bb = __ldg((const float2*)b3 + lane);
    int beg = g_row_ptr[gw], end = g_row_ptr[gw + 1];
    float2 a0 = {0.f, 0.f}, a1 = {0.f, 0.f};
    const __half2* s2 = (const __half2*)src;
    int e = beg;
    for (; e + 3 < end; e += 4) {
        int c0 = __ldg(&g_col[e]),     c1 = __ldg(&g_col[e + 1]);
        int c2 = __ldg(&g_col[e + 2]), c3 = __ldg(&g_col[e + 3]);
        float2 v0 = __half22float2(__ldg(s2 + (size_t)c0 * 32 + lane));
        float2 v1 = __half22float2(__ldg(s2 + (size_t)c1 * 32 + lane));
        float2 v2 = __half22float2(__ldg(s2 + (size_t)c2 * 32 + lane));
        float2 v3 = __half22float2(__ldg(s2 + (size_t)c3 * 32 + lane));
        a0.x += v0.x; a0.y += v0.y;
        a1.x += v1.x; a1.y += v1.y;
        a0.x += v2.x; a0.y += v2.y;
        a1.x += v3.x; a1.y += v3.y;
    }
    for (; e < end; e++) {
        int c0 = __ldg(&g_col[e]);
        float2 v0 = __half22float2(__ldg(s2 + (size_t)c0 * 32 + lane));
        a0.x += v0.x; a0.y += v0.y;
    }
    float w = g_invdeg[gw];
    float2 r;
    r.x = fmaf(a0.x + a1.x, w, bb.x);
    r.y = fmaf(a0.y + a1.y, w, bb.y);
    ((float2*)dst)[(size_t)gw * 32 + lane] = r;
}

// ---------------- GEMM (FFMA, BM=128/TM=8, KC=16, register-prefetch) ----------
// out[n][m] = sum_k A[n][k]*W[m][k] (+bias); opt BN+relu on A; opt col stats
// with fused last-block BN finalize; opt fp16 output.
template <int KD, int MD, int TN, bool BN_IN, bool STATS, bool BIAS, bool HOUT,
          int SOFF, int DIDX>
__global__ void __launch_bounds__(256, 2)
k_gemm(const float* __restrict__ A, const float* __restrict__ W,
       const float* __restrict__ bias, void* __restrict__ out, int nrows,
       const float* __restrict__ gamma, const float* __restrict__ beta) {
    constexpr int KC = 16, BM = 128, TM = 8;
    constexpr int NCH = KD / KC;
    constexpr int AIT = BM * KC / 256;   // 8
    constexpr int WIT = MD * KC / 256;   // 8 (MD=128) or 4 (MD=64)
    __shared__ __align__(16) float As[KC][BM + 4];
    __shared__ __align__(16) float Ws[KC][MD];
    __shared__ float s_sum[128];
    __shared__ float s_sq[128];
    __shared__ int s_last;

    int tid = threadIdx.x;
    int tr = tid >> 4, tc = tid & 15;
    int row0 = blockIdx.x * BM;

    float acc[TM][TN];
    #pragma unroll
    for (int i = 0; i < TM; i++)
        #pragma unroll
        for (int j = 0; j < TN; j++) acc[i][j] = 0.f;

    if (STATS && tid < MD) { s_sum[tid] = 0.f; s_sq[tid] = 0.f; }

    float pa[AIT], pw[WIT];
    // prefetch chunk 0
    #pragma unroll
    for (int it = 0; it < AIT; it++) {
        int idx = tid + it * 256;
        int k = idx & (KC - 1), r = idx >> 4;
        int gr = row0 + r;
        pa[it] = (gr < nrows) ? __ldg(&A[(size_t)gr * KD + k]) : 0.f;
    }
    #pragma unroll
    for (int it = 0; it < WIT; it++) {
        int idx = tid + it * 256;
        int k = idx & (KC - 1), c = idx >> 4;
        pw[it] = __ldg(&W[(size_t)c * KD + k]);
    }

    for (int cc = 0; cc < NCH; cc++) {
        __syncthreads();   // previous chunk's compute done -> safe to overwrite smem
        #pragma unroll
        for (int it = 0; it < AIT; it++) {
            int idx = tid + it * 256;
            int k = idx & (KC - 1), r = idx >> 4;
            float v = pa[it];
            if (BN_IN) {
                v = fmaxf(fmaf(v, __ldg(&g_ss[cc * KC + k]),
                               __ldg(&g_ss[128 + cc * KC + k])), 0.f);
            }
            As[k][r] = v;
        }
        #pragma unroll
        for (int it = 0; it < WIT; it++) {
            int idx = tid + it * 256;
            int k = idx & (KC - 1), c = idx >> 4;
            Ws[k][c] = pw[it];
        }
        __syncthreads();

        if (cc + 1 < NCH) {
            int kc = (cc + 1) * KC;
            #pragma unroll
            for (int it = 0; it < AIT; it++) {
                int idx = tid + it * 256;
                int k = idx & (KC - 1), r = idx >> 4;
                int gr = row0 + r;
                pa[it] = (gr < nrows) ? __ldg(&A[(size_t)gr * KD + kc + k]) : 0.f;
            }
            #pragma unroll
            for (int it = 0; it < WIT; it++) {
                int idx = tid + it * 256;
                int k = idx & (KC - 1), c = idx >> 4;
                pw[it] = __ldg(&W[(size_t)c * KD + kc + k]);
            }
        }

        #pragma unroll
        for (int k = 0; k < KC; k++) {
            float4 av0 = *(const float4*)&As[k][tr * TM];
            float4 av1 = *(const float4*)&As[k][tr * TM + 4];
            float a[TM] = {av0.x, av0.y, av0.z, av0.w, av1.x, av1.y, av1.z, av1.w};
            float wv[TN];
            float4 w0 = *(const float4*)&Ws[k][tc * 4];
            wv[0] = w0.x; wv[1] = w0.y; wv[2] = w0.z; wv[3] = w0.w;
            if (TN == 8) {
                float4 w1 = *(const float4*)&Ws[k][64 + tc * 4];
                wv[4] = w1.x; wv[5] = w1.y; wv[6] = w1.z; wv[7] = w1.w;
            }
            #pragma unroll
            for (int i = 0; i < TM; i++)
                #pragma unroll
                for (int j = 0; j < TN; j++)
                    acc[i][j] = fmaf(a[i], wv[j], acc[i][j]);
        }
    }

    float bj[TN];
    #pragma unroll
    for (int j = 0; j < TN; j++) {
        int c = (TN == 8) ? ((j < 4) ? tc * 4 + j : 64 + tc * 4 + (j - 4)) : tc * 4 + j;
        bj[j] = BIAS ? __ldg(&bias[c]) : 0.f;
    }

    float csum[TN], csq[TN];
    #pragma unroll
    for (int j = 0; j < TN; j++) { csum[j] = 0.f; csq[j] = 0.f; }

    #pragma unroll
    for (int i = 0; i < TM; i++) {
        int gr = row0 + tr * TM + i;
        if (gr < nrows) {
            float h[TN];
            #pragma unroll
            for (int j = 0; j < TN; j++) h[j] = acc[i][j] + bj[j];
            if (HOUT) {
                __half* oh = (__half*)out;
                __half2 p0 = __floats2half2_rn(h[0], h[1]);
                __half2 p1 = __floats2half2_rn(h[2], h[3]);
                uint2 pk;
                pk.x = *(uint32_t*)&p0; pk.y = *(uint32_t*)&p1;
                *(uint2*)&oh[(size_t)gr * MD + tc * 4] = pk;
                if (TN == 8) {
                    __half2 p2 = __floats2half2_rn(h[4], h[5]);
                    __half2 p3 = __floats2half2_rn(h[6], h[7]);
                    uint2 pk2;
                    pk2.x = *(uint32_t*)&p2; pk2.y = *(uint32_t*)&p3;
                    *(uint2*)&oh[(size_t)gr * MD + 64 + tc * 4] = pk2;
                }
            } else {
                float* of = (float*)out;
                float4 o0 = {h[0], h[1], h[2], h[3]};
                *(float4*)&of[(size_t)gr * MD + tc * 4] = o0;
                if (TN == 8) {
                    float4 o1 = {h[4], h[5], h[6], h[7]};
                    *(float4*)&of[(size_t)gr * MD + 64 + tc * 4] = o1;
                }
            }
            if (STATS) {
                #pragma unroll
                for (int j = 0; j < TN; j++) { csum[j] += h[j]; csq[j] += h[j] * h[j]; }
            }
        }
    }

    if (STATS) {
        #pragma unroll
        for (int j = 0; j < TN; j++) {
            int c = (TN == 8) ? ((j < 4) ? tc * 4 + j : 64 + tc * 4 + (j - 4)) : tc * 4 + j;
            atomicAdd(&s_sum[c], csum[j]);
            atomicAdd(&s_sq[c], csq[j]);
        }
        __syncthreads();
        if (tid < MD) {
            atomicAdd(&g_stats[SOFF + tid], s_sum[tid]);
            atomicAdd(&g_stats[SOFF + 128 + tid], s_sq[tid]);
        }
        // last-block BN finalize: scale/shift -> g_ss
        __threadfence();
        __syncthreads();
        if (tid == 0) {
            unsigned old = atomicAdd(&g_done[DIDX], 1u);
            s_last = (old == gridDim.x - 1) ? 1 : 0;
        }
        __syncthreads();
        if (s_last && tid < 128) {
            float s = __ldcg(&g_stats[SOFF + tid]);
            float q = __ldcg(&g_stats[SOFF + 128 + tid]);
            float mean = s * (1.0f / NNODES);
            float var = q * (1.0f / NNODES) - mean * mean;
            float sc = __ldg(&gamma[tid]) * rsqrtf(var + 1e-5f);
            g_ss[tid] = sc;
            g_ss[128 + tid] = fmaf(-mean, sc, __ldg(&beta[tid]));
        }
    }
}

// ---------------- launch ----------------
extern "C" void kernel_launch(void* const* d_in, const int* in_sizes, int n_in,
                              void* d_out, int out_size) {
    const float* x   = (const float*)d_in[0];
    const void*  ei  = d_in[1];
    const float* W1  = (const float*)d_in[2];
    const float* b1  = (const float*)d_in[3];
    const float* ga1 = (const float*)d_in[4];
    const float* be1 = (const float*)d_in[5];
    const float* W2  = (const float*)d_in[6];
    const float* b2  = (const float*)d_in[7];
    const float* ga2 = (const float*)d_in[8];
    const float* be2 = (const float*)d_in[9];
    const float* W3  = (const float*)d_in[10];
    const float* b3  = (const float*)d_in[11];
    float* out = (float*)d_out;

    int E = in_sizes[1] / 2;
    if (E > MAXE) E = MAXE;

    float  *bufA, *bufB;
    __half *bufH;
    cudaGetSymbolAddress((void**)&bufA, g_bufA);
    cudaGetSymbolAddress((void**)&bufB, g_bufB);
    cudaGetSymbolAddress((void**)&bufH, g_bufH);

    // frontend
    k_x2h<<<512, 256>>>(x, bufH, NNODES * 32);
    k_init<<<SCAN_NB, SCAN_BLK>>>((const unsigned int*)ei);
    k_hist<<<1024, 256>>>(ei, E);
    k_scan<<<SCAN_NB, SCAN_BLK>>>();
    k_fill<<<1024, 256>>>(ei, E);

    const int aggBlocks = (NNODES * 32 + 255) / 256;
    const int gemmBlocks = (NNODES + 127) / 128;

    // layer 1: agg(x fp16) -> bufA[N,64]; GEMM1 (+b1, stats+bnfin) -> bufH fp16
    k_agg64h<<<aggBlocks, 256>>>(bufH, bufA);
    k_gemm<64, 128, 8, false, true, true, true, 0, 0><<<gemmBlocks, 256>>>(
        bufA, W1, b1, bufH, NNODES, ga1, be1);

    // layer 2: agg(relu(BN1(h1))) -> bufA[N,128]; GEMM2 (+b2, stats+bnfin) -> bufB fp32
    k_agg128h_bn<<<aggBlocks, 256>>>(bufH, bufA);
    k_gemm<128, 128, 8, false, true, true, false, 256, 1><<<gemmBlocks, 256>>>(
        bufA, W2, b2, bufB, NNODES, ga2, be2);

    // layer 3: t = relu(BN2(h2)) @ W3^T -> bufH[N,64] fp16; agg(t)+b3 -> out
    k_gemm<128, 64, 4, true, false, false, true, 0, 0><<<gemmBlocks, 256>>>(
        bufB, W3, nullptr, bufH, NNODES, nullptr, nullptr);
    k_agg64h_bias<<<aggBlocks, 256>>>(bufH, b3, out);
}

// round 15
// speedup vs baseline: 1.1226x; 1.0144x over previous
#include <cuda_runtime.h>
#include <cuda_fp16.h>
#include <cstddef>
#include <cstdint>

#define NNODES 100000
#define MAXE   1600000
#define SCAN_BLK 1024
#define SCAN_NB  ((NNODES + SCAN_BLK - 1) / SCAN_BLK)   // 98

// ---------------- scratch (static device globals; no allocations) ----------------
__device__ __align__(16) float  g_bufA[(size_t)NNODES * 128];
__device__ __align__(16) float  g_bufB[(size_t)NNODES * 128];
__device__ __align__(16) __half g_bufH[(size_t)NNODES * 128];
__device__ int   g_cnt[NNODES];
__device__ int   g_wp[NNODES];
__device__ int   g_row_ptr[NNODES + 1];
__device__ int   g_col[MAXE];
__device__ unsigned long long g_blkp[SCAN_NB];
__device__ float g_invdeg[NNODES];
__device__ __align__(16) float g_stats[512];   // layer1: [0,256) ; layer2: [256,512)
__device__ __align__(16) float g_ss[256];      // [scale[128], shift[128]]
__device__ int   g_is64 = 1;                   // module-init; only 0 is ever written

// ---------------- fused: fp32->fp16 convert of x + frontend init ----------------
// 512x256 = 131072 threads covers NNODES/stats/detect zeroing on iteration 0.
__global__ void k_x2h_init(const float* __restrict__ src, __half* __restrict__ dst,
                           int n, const unsigned int* __restrict__ w) {
    int t = blockIdx.x * blockDim.x + threadIdx.x;
    if (t < NNODES) g_cnt[t] = 0;
    if (t < SCAN_NB) g_blkp[t] = 0ull;
    if (t < 512) g_stats[t] = 0.f;
    if (t < 2048) {
        // int64 ids < 2^31: odd 32-bit words all zero; int32: random ids.
        if (w[2 * t + 1] != 0u) g_is64 = 0;   // benign race: only writes 0
    }
    int stride = gridDim.x * blockDim.x;
    const float2* s2 = (const float2*)src;
    __half2* d2 = (__half2*)dst;
    for (int i = t; i < n; i += stride) {
        float2 v = __ldg(s2 + i);
        d2[i] = __floats2half2_rn(v.x, v.y);
    }
}

__global__ void k_hist(const void* __restrict__ ei, int E) {
    int is64 = g_is64;
    int i = blockIdx.x * blockDim.x + threadIdx.x;
    int stride = gridDim.x * blockDim.x;
    if (is64) {
        const long long* p = (const long long*)ei;
        for (; i < E; i += stride) atomicAdd(&g_cnt[(int)p[i]], 1);
    } else {
        const int* p = (const int*)ei;
        for (; i < E; i += stride) atomicAdd(&g_cnt[p[i]], 1);
    }
}

// ---------------- single-kernel decoupled scan over g_cnt ----------------
__global__ void k_scan() {
    __shared__ int wsum[32];
    __shared__ int blk_off;
    int tid = threadIdx.x, lane = tid & 31, w = tid >> 5;
    int bid = blockIdx.x;
    if (tid == 0) blk_off = 0;

    int i = bid * SCAN_BLK + tid;
    int v = (i < NNODES) ? g_cnt[i] : 0;
    int s = v;
    #pragma unroll
    for (int o = 1; o < 32; o <<= 1) {
        int t = __shfl_up_sync(0xffffffffu, s, o);
        if (lane >= o) s += t;
    }
    if (lane == 31) wsum[w] = s;
    __syncthreads();
    if (w == 0) {
        int x = wsum[lane];
        int ss = x;
        #pragma unroll
        for (int o = 1; o < 32; o <<= 1) {
            int t = __shfl_up_sync(0xffffffffu, ss, o);
            if (lane >= o) ss += t;
        }
        wsum[lane] = ss - x;
        if (lane == 31) {
            atomicExch(&g_blkp[bid], (((unsigned long long)(unsigned)ss) << 1) | 1ull);
        }
    }
    __syncthreads();

    if (tid < bid) {
        const volatile unsigned long long* p = &g_blkp[tid];
        unsigned long long pv;
        do { pv = *p; } while (!(pv & 1ull));
        atomicAdd(&blk_off, (int)(pv >> 1));
    }
    __syncthreads();

    int incl = s + wsum[w] + blk_off;
    if (i < NNODES) {
        g_row_ptr[i + 1] = incl;
        g_wp[i] = incl - v;
        g_invdeg[i] = 1.0f / ((float)v + 1e-6f);
        if (i == 0) g_row_ptr[0] = 0;
    }
}

__global__ void k_fill(const void* __restrict__ ei, int E) {
    int is64 = g_is64;
    int i = blockIdx.x * blockDim.x + threadIdx.x;
    int stride = gridDim.x * blockDim.x;
    if (is64) {
        const long long* p = (const long long*)ei;
        for (; i < E; i += stride) {
            int r = (int)p[i];
            int c = (int)p[E + i];
            int q = atomicAdd(&g_wp[r], 1);
            g_col[q] = c;
        }
    } else {
        const int* p = (const int*)ei;
        for (; i < E; i += stride) {
            int r = p[i];
            int c = p[E + i];
            int q = atomicAdd(&g_wp[r], 1);
            g_col[q] = c;
        }
    }
}

// ---------------- aggregation kernels (warp per node, fp16 gather) ------
__global__ void k_agg64h(const __half* __restrict__ src, float* __restrict__ dst) {
    int gw = (blockIdx.x * blockDim.x + threadIdx.x) >> 5;
    if (gw >= NNODES) return;
    int lane = threadIdx.x & 31;
    int beg = g_row_ptr[gw], end = g_row_ptr[gw + 1];
    float2 a0 = {0.f, 0.f}, a1 = {0.f, 0.f};
    const __half2* s2 = (const __half2*)src;
    int e = beg;
    for (; e + 3 < end; e += 4) {
        int c0 = __ldg(&g_col[e]),     c1 = __ldg(&g_col[e + 1]);
        int c2 = __ldg(&g_col[e + 2]), c3 = __ldg(&g_col[e + 3]);
        float2 v0 = __half22float2(__ldg(s2 + (size_t)c0 * 32 + lane));
        float2 v1 = __half22float2(__ldg(s2 + (size_t)c1 * 32 + lane));
        float2 v2 = __half22float2(__ldg(s2 + (size_t)c2 * 32 + lane));
        float2 v3 = __half22float2(__ldg(s2 + (size_t)c3 * 32 + lane));
        a0.x += v0.x; a0.y += v0.y;
        a1.x += v1.x; a1.y += v1.y;
        a0.x += v2.x; a0.y += v2.y;
        a1.x += v3.x; a1.y += v3.y;
    }
    for (; e < end; e++) {
        int c0 = __ldg(&g_col[e]);
        float2 v0 = __half22float2(__ldg(s2 + (size_t)c0 * 32 + lane));
        a0.x += v0.x; a0.y += v0.y;
    }
    float w = g_invdeg[gw];
    float2 r;
    r.x = (a0.x + a1.x) * w;
    r.y = (a0.y + a1.y) * w;
    ((float2*)dst)[(size_t)gw * 32 + lane] = r;
}

// 128-dim fp16 gather + BN(scale/shift)+relu on the fly, 4-edge unroll
__global__ void k_agg128h_bn(const __half* __restrict__ src, float* __restrict__ dst) {
    int gw = (blockIdx.x * blockDim.x + threadIdx.x) >> 5;
    if (gw >= NNODES) return;
    int lane = threadIdx.x & 31;
    float4 sc = *(const float4*)&g_ss[lane * 4];
    float4 sh = *(const float4*)&g_ss[128 + lane * 4];
    int beg = g_row_ptr[gw], end = g_row_ptr[gw + 1];
    float4 a0 = {0.f, 0.f, 0.f, 0.f}, a1 = {0.f, 0.f, 0.f, 0.f};
    const uint2* s8 = (const uint2*)src;   // 4 halves per lane, row = 32 uint2
    int e = beg;
    for (; e + 3 < end; e += 4) {
        int c0 = __ldg(&g_col[e]),     c1 = __ldg(&g_col[e + 1]);
        int c2 = __ldg(&g_col[e + 2]), c3 = __ldg(&g_col[e + 3]);
        uint2 u0 = __ldg(s8 + (size_t)c0 * 32 + lane);
        uint2 u1 = __ldg(s8 + (size_t)c1 * 32 + lane);
        uint2 u2 = __ldg(s8 + (size_t)c2 * 32 + lane);
        uint2 u3 = __ldg(s8 + (size_t)c3 * 32 + lane);
        float2 p00 = __half22float2(*(__half2*)&u0.x);
        float2 p01 = __half22float2(*(__half2*)&u0.y);
        float2 p10 = __half22float2(*(__half2*)&u1.x);
        float2 p11 = __half22float2(*(__half2*)&u1.y);
        float2 p20 = __half22float2(*(__half2*)&u2.x);
        float2 p21 = __half22float2(*(__half2*)&u2.y);
        float2 p30 = __half22float2(*(__half2*)&u3.x);
        float2 p31 = __half22float2(*(__half2*)&u3.y);
        a0.x += fmaxf(fmaf(p00.x, sc.x, sh.x), 0.f);
        a0.y += fmaxf(fmaf(p00.y, sc.y, sh.y), 0.f);
        a0.z += fmaxf(fmaf(p01.x, sc.z, sh.z), 0.f);
        a0.w += fmaxf(fmaf(p01.y, sc.w, sh.w), 0.f);
        a1.x += fmaxf(fmaf(p10.x, sc.x, sh.x), 0.f);
        a1.y += fmaxf(fmaf(p10.y, sc.y, sh.y), 0.f);
        a1.z += fmaxf(fmaf(p11.x, sc.z, sh.z), 0.f);
        a1.w += fmaxf(fmaf(p11.y, sc.w, sh.w), 0.f);
        a0.x += fmaxf(fmaf(p20.x, sc.x, sh.x), 0.f);
        a0.y += fmaxf(fmaf(p20.y, sc.y, sh.y), 0.f);
        a0.z += fmaxf(fmaf(p21.x, sc.z, sh.z), 0.f);
        a0.w += fmaxf(fmaf(p21.y, sc.w, sh.w), 0.f);
        a1.x += fmaxf(fmaf(p30.x, sc.x, sh.x), 0.f);
        a1.y += fmaxf(fmaf(p30.y, sc.y, sh.y), 0.f);
        a1.z += fmaxf(fmaf(p31.x, sc.z, sh.z), 0.f);
        a1.w += fmaxf(fmaf(p31.y, sc.w, sh.w), 0.f);
    }
    for (; e < end; e++) {
        int c0 = __ldg(&g_col[e]);
        uint2 u0 = __ldg(s8 + (size_t)c0 * 32 + lane);
        float2 p00 = __half22float2(*(__half2*)&u0.x);
        float2 p01 = __half22float2(*(__half2*)&u0.y);
        a0.x += fmaxf(fmaf(p00.x, sc.x, sh.x), 0.f);
        a0.y += fmaxf(fmaf(p00.y, sc.y, sh.y), 0.f);
        a0.z += fmaxf(fmaf(p01.x, sc.z, sh.z), 0.f);
        a0.w += fmaxf(fmaf(p01.y, sc.w, sh.w), 0.f);
    }
    float w = g_invdeg[gw];
    float4 r;
    r.x = (a0.x + a1.x) * w;
    r.y = (a0.y + a1.y) * w;
    r.z = (a0.z + a1.z) * w;
    r.w = (a0.w + a1.w) * w;
    ((float4*)dst)[(size_t)gw * 32 + lane] = r;
}

// final: fp16 gather of t [N,64], add bias b3 -> d_out (fp32)
__global__ void k_agg64h_bias(const __half* __restrict__ src,
                              const float* __restrict__ b3,
                              float* __restrict__ dst) {
    int gw = (blockIdx.x * blockDim.x + threadIdx.x) >> 5;
    if (gw >= NNODES) return;
    int lane = threadIdx.x & 31;
    float2 bb = __ldg((const float2*)b3 + lane);
    int beg = g_row_ptr[gw], end = g_row_ptr[gw + 1];
    float2 a0 = {0.f, 0.f}, a1 = {0.f, 0.f};
    const __half2* s2 = (const __half2*)src;
    int e = beg;
    for (; e + 3 < end; e += 4) {
        int c0 = __ldg(&g_col[e]),     c1 = __ldg(&g_col[e + 1]);
        int c2 = __ldg(&g_col[e + 2]), c3 = __ldg(&g_col[e + 3]);
        float2 v0 = __half22float2(__ldg(s2 + (size_t)c0 * 32 + lane));
        float2 v1 = __half22float2(__ldg(s2 + (size_t)c1 * 32 + lane));
        float2 v2 = __half22float2(__ldg(s2 + (size_t)c2 * 32 + lane));
        float2 v3 = __half22float2(__ldg(s2 + (size_t)c3 * 32 + lane));
        a0.x += v0.x; a0.y += v0.y;
        a1.x += v1.x; a1.y += v1.y;
        a0.x += v2.x; a0.y += v2.y;
        a1.x += v3.x; a1.y += v3.y;
    }
    for (; e < end; e++) {
        int c0 = __ldg(&g_col[e]);
        float2 v0 = __half22float2(__ldg(s2 + (size_t)c0 * 32 + lane));
        a0.x += v0.x; a0.y += v0.y;
    }
    float w = g_invdeg[gw];
    float2 r;
    r.x = fmaf(a0.x + a1.x, w, bb.x);
    r.y = fmaf(a0.y + a1.y, w, bb.y);
    ((float2*)dst)[(size_t)gw * 32 + lane] = r;
}

// ---------------- GEMM (FFMA, BM=128/TM=8, KC=16, register-prefetch) ----------
// out[n][m] = sum_k A[n][k]*W[m][k] (+bias); opt BN+relu on A; opt col stats;
// opt fp16 output. Chunk c+1's global loads overlap chunk c's compute.
template <int KD, int MD, int TN, bool BN_IN, bool STATS, bool BIAS, bool HOUT, int SOFF>
__global__ void __launch_bounds__(256, 2)
k_gemm(const float* __restrict__ A, const float* __restrict__ W,
       const float* __restrict__ bias, void* __restrict__ out, int nrows) {
    constexpr int KC = 16, BM = 128, TM = 8;
    constexpr int NCH = KD / KC;
    constexpr int AIT = BM * KC / 256;   // 8
    constexpr int WIT = MD * KC / 256;   // 8 (MD=128) or 4 (MD=64)
    __shared__ __align__(16) float As[KC][BM + 4];
    __shared__ __align__(16) float Ws[KC][MD];
    __shared__ float s_sum[128];
    __shared__ float s_sq[128];

    int tid = threadIdx.x;
    int tr = tid >> 4, tc = tid & 15;
    int row0 = blockIdx.x * BM;

    float acc[TM][TN];
    #pragma unroll
    for (int i = 0; i < TM; i++)
        #pragma unroll
        for (int j = 0; j < TN; j++) acc[i][j] = 0.f;

    if (STATS && tid < MD) { s_sum[tid] = 0.f; s_sq[tid] = 0.f; }

    float pa[AIT], pw[WIT];
    // prefetch chunk 0
    #pragma unroll
    for (int it = 0; it < AIT; it++) {
        int idx = tid + it * 256;
        int k = idx & (KC - 1), r = idx >> 4;
        int gr = row0 + r;
        pa[it] = (gr < nrows) ? __ldg(&A[(size_t)gr * KD + k]) : 0.f;
    }
    #pragma unroll
    for (int it = 0; it < WIT; it++) {
        int idx = tid + it * 256;
        int k = idx & (KC - 1), c = idx >> 4;
        pw[it] = __ldg(&W[(size_t)c * KD + k]);
    }

    for (int cc = 0; cc < NCH; cc++) {
        __syncthreads();   // previous chunk's compute done -> safe to overwrite smem
        #pragma unroll
        for (int it = 0; it < AIT; it++) {
            int idx = tid + it * 256;
            int k = idx & (KC - 1), r = idx >> 4;
            float v = pa[it];
            if (BN_IN) {
                v = fmaxf(fmaf(v, __ldg(&g_ss[cc * KC + k]),
                               __ldg(&g_ss[128 + cc * KC + k])), 0.f);
            }
            As[k][r] = v;
        }
        #pragma unroll
        for (int it = 0; it < WIT; it++) {
            int idx = tid + it * 256;
            int k = idx & (KC - 1), c = idx >> 4;
            Ws[k][c] = pw[it];
        }
        __syncthreads();

        if (cc + 1 < NCH) {
            int kc = (cc + 1) * KC;
            #pragma unroll
            for (int it = 0; it < AIT; it++) {
                int idx = tid + it * 256;
                int k = idx & (KC - 1), r = idx >> 4;
                int gr = row0 + r;
                pa[it] = (gr < nrows) ? __ldg(&A[(size_t)gr * KD + kc + k]) : 0.f;
            }
            #pragma unroll
            for (int it = 0; it < WIT; it++) {
                int idx = tid + it * 256;
                int k = idx & (KC - 1), c = idx >> 4;
                pw[it] = __ldg(&W[(size_t)c * KD + kc + k]);
            }
        }

        #pragma unroll
        for (int k = 0; k < KC; k++) {
            float4 av0 = *(const float4*)&As[k][tr * TM];
            float4 av1 = *(const float4*)&As[k][tr * TM + 4];
            float a[TM] = {av0.x, av0.y, av0.z, av0.w, av1.x, av1.y, av1.z, av1.w};
            float wv[TN];
            float4 w0 = *(const float4*)&Ws[k][tc * 4];
            wv[0] = w0.x; wv[1] = w0.y; wv[2] = w0.z; wv[3] = w0.w;
            if (TN == 8) {
                float4 w1 = *(const float4*)&Ws[k][64 + tc * 4];
                wv[4] = w1.x; wv[5] = w1.y; wv[6] = w1.z; wv[7] = w1.w;
            }
            #pragma unroll
            for (int i = 0; i < TM; i++)
                #pragma unroll
                for (int j = 0; j < TN; j++)
                    acc[i][j] = fmaf(a[i], wv[j], acc[i][j]);
        }
    }

    float bj[TN];
    #pragma unroll
    for (int j = 0; j < TN; j++) {
        int c = (TN == 8) ? ((j < 4) ? tc * 4 + j : 64 + tc * 4 + (j - 4)) : tc * 4 + j;
        bj[j] = BIAS ? __ldg(&bias[c]) : 0.f;
    }

    float csum[TN], csq[TN];
    #pragma unroll
    for (int j = 0; j < TN; j++) { csum[j] = 0.f; csq[j] = 0.f; }

    #pragma unroll
    for (int i = 0; i < TM; i++) {
        int gr = row0 + tr * TM + i;
        if (gr < nrows) {
            float h[TN];
            #pragma unroll
            for (int j = 0; j < TN; j++) h[j] = acc[i][j] + bj[j];
            if (HOUT) {
                __half* oh = (__half*)out;
                __half2 p0 = __floats2half2_rn(h[0], h[1]);
                __half2 p1 = __floats2half2_rn(h[2], h[3]);
                uint2 pk;
                pk.x = *(uint32_t*)&p0; pk.y = *(uint32_t*)&p1;
                *(uint2*)&oh[(size_t)gr * MD + tc * 4] = pk;
                if (TN == 8) {
                    __half2 p2 = __floats2half2_rn(h[4], h[5]);
                    __half2 p3 = __floats2half2_rn(h[6], h[7]);
                    uint2 pk2;
                    pk2.x = *(uint32_t*)&p2; pk2.y = *(uint32_t*)&p3;
                    *(uint2*)&oh[(size_t)gr * MD + 64 + tc * 4] = pk2;
                }
            } else {
                float* of = (float*)out;
                float4 o0 = {h[0], h[1], h[2], h[3]};
                *(float4*)&of[(size_t)gr * MD + tc * 4] = o0;
                if (TN == 8) {
                    float4 o1 = {h[4], h[5], h[6], h[7]};
                    *(float4*)&of[(size_t)gr * MD + 64 + tc * 4] = o1;
                }
            }
            if (STATS) {
                #pragma unroll
                for (int j = 0; j < TN; j++) { csum[j] += h[j]; csq[j] += h[j] * h[j]; }
            }
        }
    }

    if (STATS) {
        #pragma unroll
        for (int j = 0; j < TN; j++) {
            int c = (TN == 8) ? ((j < 4) ? tc * 4 + j : 64 + tc * 4 + (j - 4)) : tc * 4 + j;
            atomicAdd(&s_sum[c], csum[j]);
            atomicAdd(&s_sq[c], csq[j]);
        }
        __syncthreads();
        if (tid < MD) {
            atomicAdd(&g_stats[SOFF + tid], s_sum[tid]);
            atomicAdd(&g_stats[SOFF + 128 + tid], s_sq[tid]);
        }
    }
}

__global__ void k_bnfin(const float* __restrict__ gamma,
                        const float* __restrict__ beta, int soff) {
    int c = threadIdx.x;
    if (c < 128) {
        float s = g_stats[soff + c], q = g_stats[soff + 128 + c];
        float mean = s * (1.0f / NNODES);
        float var = q * (1.0f / NNODES) - mean * mean;
        float sc = __ldg(&gamma[c]) * rsqrtf(var + 1e-5f);
        g_ss[c] = sc;
        g_ss[128 + c] = fmaf(-mean, sc, __ldg(&beta[c]));
    }
}

// ---------------- launch ----------------
extern "C" void kernel_launch(void* const* d_in, const int* in_sizes, int n_in,
                              void* d_out, int out_size) {
    const float* x   = (const float*)d_in[0];
    const void*  ei  = d_in[1];
    const float* W1  = (const float*)d_in[2];
    const float* b1  = (const float*)d_in[3];
    const float* ga1 = (const float*)d_in[4];
    const float* be1 = (const float*)d_in[5];
    const float* W2  = (const float*)d_in[6];
    const float* b2  = (const float*)d_in[7];
    const float* ga2 = (const float*)d_in[8];
    const float* be2 = (const float*)d_in[9];
    const float* W3  = (const float*)d_in[10];
    const float* b3  = (const float*)d_in[11];
    float* out = (float*)d_out;

    int E = in_sizes[1] / 2;
    if (E > MAXE) E = MAXE;

    float  *bufA, *bufB;
    __half *bufH;
    cudaGetSymbolAddress((void**)&bufA, g_bufA);
    cudaGetSymbolAddress((void**)&bufB, g_bufB);
    cudaGetSymbolAddress((void**)&bufH, g_bufH);

    // frontend (4 launches: x2h+init fused, hist, scan, fill)
    k_x2h_init<<<512, 256>>>(x, bufH, NNODES * 32, (const unsigned int*)ei);
    k_hist<<<1024, 256>>>(ei, E);
    k_scan<<<SCAN_NB, SCAN_BLK>>>();
    k_fill<<<1024, 256>>>(ei, E);

    const int aggBlocks = (NNODES * 32 + 255) / 256;
    const int gemmBlocks = (NNODES + 127) / 128;

    // layer 1: agg(x fp16) -> bufA[N,64]; GEMM1 (+b1, stats) -> bufH[N,128] fp16
    k_agg64h<<<aggBlocks, 256>>>(bufH, bufA);
    k_gemm<64, 128, 8, false, true, true, true, 0><<<gemmBlocks, 256>>>(bufA, W1, b1, bufH, NNODES);
    k_bnfin<<<1, 128>>>(ga1, be1, 0);

    // layer 2: agg(relu(BN1(h1))) from fp16 -> bufA[N,128]; GEMM2 -> bufB[N,128] fp32
    k_agg128h_bn<<<aggBlocks, 256>>>(bufH, bufA);
    k_gemm<128, 128, 8, false, true, true, false, 256><<<gemmBlocks, 256>>>(bufA, W2, b2, bufB, NNODES);
    k_bnfin<<<1, 128>>>(ga2, be2, 256);

    // layer 3: t = relu(BN2(h2)) @ W3^T -> bufH[N,64] fp16; agg(t)+b3 -> out
    k_gemm<128, 64, 4, true, false, false, true, 0><<<gemmBlocks, 256>>>(bufB, W3, nullptr, bufH, NNODES);
    k_agg64h_bias<<<aggBlocks, 256>>>(bufH, b3, out);
}

// round 16
// speedup vs baseline: 1.1272x; 1.0041x over previous
#include <cuda_runtime.h>
#include <cuda_fp16.h>
#include <cstddef>
#include <cstdint>

#define NNODES 100000
#define MAXE   1600000
#define SCAN_BLK 1024
#define SCAN_NB  ((NNODES + SCAN_BLK - 1) / SCAN_BLK)   // 98

// ---------------- scratch (static device globals; no allocations) ----------------
// NOTE: g_cnt relies on the module-load zero-init + k_scan restoring zeros after
// use, so k_x2h_hist never needs to clear it.
__device__ __align__(16) float  g_bufB[(size_t)NNODES * 128];
__device__ __align__(16) __half g_bufH[(size_t)NNODES * 128];
__device__ __align__(16) __half g_bufHA[(size_t)NNODES * 128];
__device__ int   g_cnt[NNODES];
__device__ int   g_wp[NNODES];
__device__ int   g_row_ptr[NNODES + 1];
__device__ int   g_col[MAXE];
__device__ unsigned long long g_blkp[SCAN_NB];
__device__ float g_invdeg[NNODES];
__device__ __align__(16) float g_stats[512];   // layer1: [0,256) ; layer2: [256,512)
__device__ __align__(16) float g_ss[256];      // [scale[128], shift[128]]
__device__ int   g_is64 = 1;                   // module-init; only 0 is ever written

// ---------------- fused frontend: init + x fp32->fp16 + row histogram ----------
// g_cnt is zero on entry (module init / restored by k_scan each launch).
__global__ void k_x2h_hist(const float* __restrict__ src, __half* __restrict__ dst,
                           int n, const void* __restrict__ ei, int E) {
    __shared__ int s_is64;
    int t = blockIdx.x * blockDim.x + threadIdx.x;
    if (t < SCAN_NB) g_blkp[t] = 0ull;
    if (t < 512) g_stats[t] = 0.f;
    if (threadIdx.x == 0) {
        // int64 ids < 2^31: odd 32-bit words of first 16 elements all zero.
        const unsigned int* w = (const unsigned int*)ei;
        unsigned acc = 0u;
        #pragma unroll
        for (int j = 0; j < 16; j++) acc |= w[2 * j + 1];
        s_is64 = (acc == 0u) ? 1 : 0;
        if (blockIdx.x == 0 && acc != 0u) g_is64 = 0;   // only-0 write
    }
    int stride = gridDim.x * blockDim.x;
    const float2* s2 = (const float2*)src;
    __half2* d2 = (__half2*)dst;
    for (int i = t; i < n; i += stride) {
        float2 v = __ldg(s2 + i);
        d2[i] = __floats2half2_rn(v.x, v.y);
    }
    __syncthreads();
    if (s_is64) {
        const long long* p = (const long long*)ei;
        for (int e = t; e < E; e += stride) atomicAdd(&g_cnt[(int)p[e]], 1);
    } else {
        const int* p = (const int*)ei;
        for (int e = t; e < E; e += stride) atomicAdd(&g_cnt[p[e]], 1);
    }
}

// ---------------- single-kernel decoupled scan over g_cnt (restores zeros) -----
__global__ void k_scan() {
    __shared__ int wsum[32];
    __shared__ int blk_off;
    int tid = threadIdx.x, lane = tid & 31, w = tid >> 5;
    int bid = blockIdx.x;
    if (tid == 0) blk_off = 0;

    int i = bid * SCAN_BLK + tid;
    int v = (i < NNODES) ? g_cnt[i] : 0;
    if (i < NNODES) g_cnt[i] = 0;      // restore invariant for next launch
    int s = v;
    #pragma unroll
    for (int o = 1; o < 32; o <<= 1) {
        int t = __shfl_up_sync(0xffffffffu, s, o);
        if (lane >= o) s += t;
    }
    if (lane == 31) wsum[w] = s;
    __syncthreads();
    if (w == 0) {
        int x = wsum[lane];
        int ss = x;
        #pragma unroll
        for (int o = 1; o < 32; o <<= 1) {
            int t = __shfl_up_sync(0xffffffffu, ss, o);
            if (lane >= o) ss += t;
        }
        wsum[lane] = ss - x;
        if (lane == 31) {
            atomicExch(&g_blkp[bid], (((unsigned long long)(unsigned)ss) << 1) | 1ull);
        }
    }
    __syncthreads();

    if (tid < bid) {
        const volatile unsigned long long* p = &g_blkp[tid];
        unsigned long long pv;
        do { pv = *p; } while (!(pv & 1ull));
        atomicAdd(&blk_off, (int)(pv >> 1));
    }
    __syncthreads();

    int incl = s + wsum[w] + blk_off;
    if (i < NNODES) {
        g_row_ptr[i + 1] = incl;
        g_wp[i] = incl - v;
        g_invdeg[i] = 1.0f / ((float)v + 1e-6f);
        if (i == 0) g_row_ptr[0] = 0;
    }
}

__global__ void k_fill(const void* __restrict__ ei, int E) {
    int is64 = g_is64;
    int i = blockIdx.x * blockDim.x + threadIdx.x;
    int stride = gridDim.x * blockDim.x;
    if (is64) {
        const long long* p = (const long long*)ei;
        for (; i < E; i += stride) {
            int r = (int)p[i];
            int c = (int)p[E + i];
            int q = atomicAdd(&g_wp[r], 1);
            g_col[q] = c;
        }
    } else {
        const int* p = (const int*)ei;
        for (; i < E; i += stride) {
            int r = p[i];
            int c = p[E + i];
            int q = atomicAdd(&g_wp[r], 1);
            g_col[q] = c;
        }
    }
}

// ---------------- aggregation kernels (warp per node, fp16 in AND out) ------
__global__ void k_agg64h(const __half* __restrict__ src, __half* __restrict__ dst) {
    int gw = (blockIdx.x * blockDim.x + threadIdx.x) >> 5;
    if (gw >= NNODES) return;
    int lane = threadIdx.x & 31;
    int beg = g_row_ptr[gw], end = g_row_ptr[gw + 1];
    float2 a0 = {0.f, 0.f}, a1 = {0.f, 0.f};
    const __half2* s2 = (const __half2*)src;
    int e = beg;
    for (; e + 3 < end; e += 4) {
        int c0 = __ldg(&g_col[e]),     c1 = __ldg(&g_col[e + 1]);
        int c2 = __ldg(&g_col[e + 2]), c3 = __ldg(&g_col[e + 3]);
        float2 v0 = __half22float2(__ldg(s2 + (size_t)c0 * 32 + lane));
        float2 v1 = __half22float2(__ldg(s2 + (size_t)c1 * 32 + lane));
        float2 v2 = __half22float2(__ldg(s2 + (size_t)c2 * 32 + lane));
        float2 v3 = __half22float2(__ldg(s2 + (size_t)c3 * 32 + lane));
        a0.x += v0.x; a0.y += v0.y;
        a1.x += v1.x; a1.y += v1.y;
        a0.x += v2.x; a0.y += v2.y;
        a1.x += v3.x; a1.y += v3.y;
    }
    for (; e < end; e++) {
        int c0 = __ldg(&g_col[e]);
        float2 v0 = __half22float2(__ldg(s2 + (size_t)c0 * 32 + lane));
        a0.x += v0.x; a0.y += v0.y;
    }
    float w = g_invdeg[gw];
    ((__half2*)dst)[(size_t)gw * 32 + lane] =
        __floats2half2_rn((a0.x + a1.x) * w, (a0.y + a1.y) * w);
}

// 128-dim fp16 gather + BN(scale/shift)+relu on the fly -> fp16 out
__global__ void k_agg128h_bn(const __half* __restrict__ src, __half* __restrict__ dst) {
    int gw = (blockIdx.x * blockDim.x + threadIdx.x) >> 5;
    if (gw >= NNODES) return;
    int lane = threadIdx.x & 31;
    float4 sc = *(const float4*)&g_ss[lane * 4];
    float4 sh = *(const float4*)&g_ss[128 + lane * 4];
    int beg = g_row_ptr[gw], end = g_row_ptr[gw + 1];
    float4 a0 = {0.f, 0.f, 0.f, 0.f}, a1 = {0.f, 0.f, 0.f, 0.f};
    const uint2* s8 = (const uint2*)src;   // 4 halves per lane, row = 32 uint2
    int e = beg;
    for (; e + 3 < end; e += 4) {
        int c0 = __ldg(&g_col[e]),     c1 = __ldg(&g_col[e + 1]);
        int c2 = __ldg(&g_col[e + 2]), c3 = __ldg(&g_col[e + 3]);
        uint2 u0 = __ldg(s8 + (size_t)c0 * 32 + lane);
        uint2 u1 = __ldg(s8 + (size_t)c1 * 32 + lane);
        uint2 u2 = __ldg(s8 + (size_t)c2 * 32 + lane);
        uint2 u3 = __ldg(s8 + (size_t)c3 * 32 + lane);
        float2 p00 = __half22float2(*(__half2*)&u0.x);
        float2 p01 = __half22float2(*(__half2*)&u0.y);
        float2 p10 = __half22float2(*(__half2*)&u1.x);
        float2 p11 = __half22float2(*(__half2*)&u1.y);
        float2 p20 = __half22float2(*(__half2*)&u2.x);
        float2 p21 = __half22float2(*(__half2*)&u2.y);
        float2 p30 = __half22float2(*(__half2*)&u3.x);
        float2 p31 = __half22float2(*(__half2*)&u3.y);
        a0.x += fmaxf(fmaf(p00.x, sc.x, sh.x), 0.f);
        a0.y += fmaxf(fmaf(p00.y, sc.y, sh.y), 0.f);
        a0.z += fmaxf(fmaf(p01.x, sc.z, sh.z), 0.f);
        a0.w += fmaxf(fmaf(p01.y, sc.w, sh.w), 0.f);
        a1.x += fmaxf(fmaf(p10.x, sc.x, sh.x), 0.f);
        a1.y += fmaxf(fmaf(p10.y, sc.y, sh.y), 0.f);
        a1.z += fmaxf(fmaf(p11.x, sc.z, sh.z), 0.f);
        a1.w += fmaxf(fmaf(p11.y, sc.w, sh.w), 0.f);
        a0.x += fmaxf(fmaf(p20.x, sc.x, sh.x), 0.f);
        a0.y += fmaxf(fmaf(p20.y, sc.y, sh.y), 0.f);
        a0.z += fmaxf(fmaf(p21.x, sc.z, sh.z), 0.f);
        a0.w += fmaxf(fmaf(p21.y, sc.w, sh.w), 0.f);
        a1.x += fmaxf(fmaf(p30.x, sc.x, sh.x), 0.f);
        a1.y += fmaxf(fmaf(p30.y, sc.y, sh.y), 0.f);
        a1.z += fmaxf(fmaf(p31.x, sc.z, sh.z), 0.f);
        a1.w += fmaxf(fmaf(p31.y, sc.w, sh.w), 0.f);
    }
    for (; e < end; e++) {
        int c0 = __ldg(&g_col[e]);
        uint2 u0 = __ldg(s8 + (size_t)c0 * 32 + lane);
        float2 p00 = __half22float2(*(__half2*)&u0.x);
        float2 p01 = __half22float2(*(__half2*)&u0.y);
        a0.x += fmaxf(fmaf(p00.x, sc.x, sh.x), 0.f);
        a0.y += fmaxf(fmaf(p00.y, sc.y, sh.y), 0.f);
        a0.z += fmaxf(fmaf(p01.x, sc.z, sh.z), 0.f);
        a0.w += fmaxf(fmaf(p01.y, sc.w, sh.w), 0.f);
    }
    float w = g_invdeg[gw];
    __half2 r0 = __floats2half2_rn((a0.x + a1.x) * w, (a0.y + a1.y) * w);
    __half2 r1 = __floats2half2_rn((a0.z + a1.z) * w, (a0.w + a1.w) * w);
    uint2 pk;
    pk.x = *(uint32_t*)&r0; pk.y = *(uint32_t*)&r1;
    ((uint2*)dst)[(size_t)gw * 32 + lane] = pk;
}

// final: fp16 gather of t [N,64], add bias b3 -> d_out (fp32)
__global__ void k_agg64h_bias(const __half* __restrict__ src,
                              const float* __restrict__ b3,
                              float* __restrict__ dst) {
    int gw = (blockIdx.x * blockDim.x + threadIdx.x) >> 5;
    if (gw >= NNODES) return;
    int lane = threadIdx.x & 31;
    float2 bb = __ldg((const float2*)b3 + lane);
    int beg = g_row_ptr[gw], end = g_row_ptr[gw + 1];
    float2 a0 = {0.f, 0.f}, a1 = {0.f, 0.f};
    const __half2* s2 = (const __half2*)src;
    int e = beg;
    for (; e + 3 < end; e += 4) {
        int c0 = __ldg(&g_col[e]),     c1 = __ldg(&g_col[e + 1]);
        int c2 = __ldg(&g_col[e + 2]), c3 = __ldg(&g_col[e + 3]);
        float2 v0 = __half22float2(__ldg(s2 + (size_t)c0 * 32 + lane));
        float2 v1 = __half22float2(__ldg(s2 + (size_t)c1 * 32 + lane));
        float2 v2 = __half22float2(__ldg(s2 + (size_t)c2 * 32 + lane));
        float2 v3 = __half22float2(__ldg(s2 + (size_t)c3 * 32 + lane));
        a0.x += v0.x; a0.y += v0.y;
        a1.x += v1.x; a1.y += v1.y;
        a0.x += v2.x; a0.y += v2.y;
        a1.x += v3.x; a1.y += v3.y;
    }
    for (; e < end; e++) {
        int c0 = __ldg(&g_col[e]);
        float2 v0 = __half22float2(__ldg(s2 + (size_t)c0 * 32 + lane));
        a0.x += v0.x; a0.y += v0.y;
    }
    float w = g_invdeg[gw];
    float2 r;
    r.x = fmaf(a0.x + a1.x, w, bb.x);
    r.y = fmaf(a0.y + a1.y, w, bb.y);
    ((float2*)dst)[(size_t)gw * 32 + lane] = r;
}

// ---------------- GEMM (FFMA, BM=128/TM=8, KC=16, register-prefetch) ----------
// out[n][m] = sum_k A[n][k]*W[m][k] (+bias); A fp32 or fp16 (AHALF); opt BN+relu
// on A; opt col stats; opt fp16 output.
template <int KD, int MD, int TN, bool AHALF, bool BN_IN, bool STATS, bool BIAS,
          bool HOUT, int SOFF>
__global__ void __launch_bounds__(256, 2)
k_gemm(const void* __restrict__ A, const float* __restrict__ W,
       const float* __restrict__ bias, void* __restrict__ out, int nrows) {
    constexpr int KC = 16, BM = 128, TM = 8;
    constexpr int NCH = KD / KC;
    constexpr int AIT = BM * KC / 256;   // 8
    constexpr int WIT = MD * KC / 256;   // 8 (MD=128) or 4 (MD=64)
    __shared__ __align__(16) float As[KC][BM + 4];
    __shared__ __align__(16) float Ws[KC][MD];
    __shared__ float s_sum[128];
    __shared__ float s_sq[128];

    int tid = threadIdx.x;
    int tr = tid >> 4, tc = tid & 15;
    int row0 = blockIdx.x * BM;

    float acc[TM][TN];
    #pragma unroll
    for (int i = 0; i < TM; i++)
        #pragma unroll
        for (int j = 0; j < TN; j++) acc[i][j] = 0.f;

    if (STATS && tid < MD) { s_sum[tid] = 0.f; s_sq[tid] = 0.f; }

    float pa[AIT], pw[WIT];
    // prefetch chunk 0
    #pragma unroll
    for (int it = 0; it < AIT; it++) {
        int idx = tid + it * 256;
        int k = idx & (KC - 1), r = idx >> 4;
        int gr = row0 + r;
        float v = 0.f;
        if (gr < nrows) {
            if (AHALF) v = __half2float(__ldg(&((const __half*)A)[(size_t)gr * KD + k]));
            else       v = __ldg(&((const float*)A)[(size_t)gr * KD + k]);
        }
        pa[it] = v;
    }
    #pragma unroll
    for (int it = 0; it < WIT; it++) {
        int idx = tid + it * 256;
        int k = idx & (KC - 1), c = idx >> 4;
        pw[it] = __ldg(&W[(size_t)c * KD + k]);
    }

    for (int cc = 0; cc < NCH; cc++) {
        __syncthreads();   // previous chunk's compute done -> safe to overwrite smem
        #pragma unroll
        for (int it = 0; it < AIT; it++) {
            int idx = tid + it * 256;
            int k = idx & (KC - 1), r = idx >> 4;
            float v = pa[it];
            if (BN_IN) {
                v = fmaxf(fmaf(v, __ldg(&g_ss[cc * KC + k]),
                               __ldg(&g_ss[128 + cc * KC + k])), 0.f);
            }
            As[k][r] = v;
        }
        #pragma unroll
        for (int it = 0; it < WIT; it++) {
            int idx = tid + it * 256;
            int k = idx & (KC - 1), c = idx >> 4;
            Ws[k][c] = pw[it];
        }
        __syncthreads();

        if (cc + 1 < NCH) {
            int kc = (cc + 1) * KC;
            #pragma unroll
            for (int it = 0; it < AIT; it++) {
                int idx = tid + it * 256;
                int k = idx & (KC - 1), r = idx >> 4;
                int gr = row0 + r;
                float v = 0.f;
                if (gr < nrows) {
                    if (AHALF) v = __half2float(__ldg(&((const __half*)A)[(size_t)gr * KD + kc + k]));
                    else       v = __ldg(&((const float*)A)[(size_t)gr * KD + kc + k]);
                }
                pa[it] = v;
            }
            #pragma unroll
            for (int it = 0; it < WIT; it++) {
                int idx = tid + it * 256;
                int k = idx & (KC - 1), c = idx >> 4;
                pw[it] = __ldg(&W[(size_t)c * KD + kc + k]);
            }
        }

        #pragma unroll
        for (int k = 0; k < KC; k++) {
            float4 av0 = *(const float4*)&As[k][tr * TM];
            float4 av1 = *(const float4*)&As[k][tr * TM + 4];
            float a[TM] = {av0.x, av0.y, av0.z, av0.w, av1.x, av1.y, av1.z, av1.w};
            float wv[TN];
            float4 w0 = *(const float4*)&Ws[k][tc * 4];
            wv[0] = w0.x; wv[1] = w0.y; wv[2] = w0.z; wv[3] = w0.w;
            if (TN == 8) {
                float4 w1 = *(const float4*)&Ws[k][64 + tc * 4];
                wv[4] = w1.x; wv[5] = w1.y; wv[6] = w1.z; wv[7] = w1.w;
            }
            #pragma unroll
            for (int i = 0; i < TM; i++)
                #pragma unroll
                for (int j = 0; j < TN; j++)
                    acc[i][j] = fmaf(a[i], wv[j], acc[i][j]);
        }
    }

    float bj[TN];
    #pragma unroll
    for (int j = 0; j < TN; j++) {
        int c = (TN == 8) ? ((j < 4) ? tc * 4 + j : 64 + tc * 4 + (j - 4)) : tc * 4 + j;
        bj[j] = BIAS ? __ldg(&bias[c]) : 0.f;
    }

    float csum[TN], csq[TN];
    #pragma unroll
    for (int j = 0; j < TN; j++) { csum[j] = 0.f; csq[j] = 0.f; }

    #pragma unroll
    for (int i = 0; i < TM; i++) {
        int gr = row0 + tr * TM + i;
        if (gr < nrows) {
            float h[TN];
            #pragma unroll
            for (int j = 0; j < TN; j++) h[j] = acc[i][j] + bj[j];
            if (HOUT) {
                __half* oh = (__half*)out;
                __half2 p0 = __floats2half2_rn(h[0], h[1]);
                __half2 p1 = __floats2half2_rn(h[2], h[3]);
                uint2 pk;
                pk.x = *(uint32_t*)&p0; pk.y = *(uint32_t*)&p1;
                *(uint2*)&oh[(size_t)gr * MD + tc * 4] = pk;
                if (TN == 8) {
                    __half2 p2 = __floats2half2_rn(h[4], h[5]);
                    __half2 p3 = __floats2half2_rn(h[6], h[7]);
                    uint2 pk2;
                    pk2.x = *(uint32_t*)&p2; pk2.y = *(uint32_t*)&p3;
                    *(uint2*)&oh[(size_t)gr * MD + 64 + tc * 4] = pk2;
                }
            } else {
                float* of = (float*)out;
                float4 o0 = {h[0], h[1], h[2], h[3]};
                *(float4*)&of[(size_t)gr * MD + tc * 4] = o0;
                if (TN == 8) {
                    float4 o1 = {h[4], h[5], h[6], h[7]};
                    *(float4*)&of[(size_t)gr * MD + 64 + tc * 4] = o1;
                }
            }
            if (STATS) {
                #pragma unroll
                for (int j = 0; j < TN; j++) { csum[j] += h[j]; csq[j] += h[j] * h[j]; }
            }
        }
    }

    if (STATS) {
        #pragma unroll
        for (int j = 0; j < TN; j++) {
            int c = (TN == 8) ? ((j < 4) ? tc * 4 + j : 64 + tc * 4 + (j - 4)) : tc * 4 + j;
            atomicAdd(&s_sum[c], csum[j]);
            atomicAdd(&s_sq[c], csq[j]);
        }
        __syncthreads();
        if (tid < MD) {
            atomicAdd(&g_stats[SOFF + tid], s_sum[tid]);
            atomicAdd(&g_stats[SOFF + 128 + tid], s_sq[tid]);
        }
    }
}

__global__ void k_bnfin(const float* __restrict__ gamma,
                        const float* __restrict__ beta, int soff) {
    int c = threadIdx.x;
    if (c < 128) {
        float s = g_stats[soff + c], q = g_stats[soff + 128 + c];
        float mean = s * (1.0f / NNODES);
        float var = q * (1.0f / NNODES) - mean * mean;
        float sc = __ldg(&gamma[c]) * rsqrtf(var + 1e-5f);
        g_ss[c] = sc;
        g_ss[128 + c] = fmaf(-mean, sc, __ldg(&beta[c]));
    }
}

// ---------------- launch ----------------
extern "C" void kernel_launch(void* const* d_in, const int* in_sizes, int n_in,
                              void* d_out, int out_size) {
    const float* x   = (const float*)d_in[0];
    const void*  ei  = d_in[1];
    const float* W1  = (const float*)d_in[2];
    const float* b1  = (const float*)d_in[3];
    const float* ga1 = (const float*)d_in[4];
    const float* be1 = (const float*)d_in[5];
    const float* W2  = (const float*)d_in[6];
    const float* b2  = (const float*)d_in[7];
    const float* ga2 = (const float*)d_in[8];
    const float* be2 = (const float*)d_in[9];
    const float* W3  = (const float*)d_in[10];
    const float* b3  = (const float*)d_in[11];
    float* out = (float*)d_out;

    int E = in_sizes[1] / 2;
    if (E > MAXE) E = MAXE;

    float  *bufB;
    __half *bufH, *bufHA;
    cudaGetSymbolAddress((void**)&bufB, g_bufB);
    cudaGetSymbolAddress((void**)&bufH, g_bufH);
    cudaGetSymbolAddress((void**)&bufHA, g_bufHA);

    // frontend (3 launches: x2h+init+hist fused, scan, fill)
    k_x2h_hist<<<512, 256>>>(x, bufH, NNODES * 32, ei, E);
    k_scan<<<SCAN_NB, SCAN_BLK>>>();
    k_fill<<<1024, 256>>>(ei, E);

    const int aggBlocks = (NNODES * 32 + 255) / 256;
    const int gemmBlocks = (NNODES + 127) / 128;

    // layer 1: agg(x fp16) -> bufHA[N,64] fp16; GEMM1 (+b1, stats) -> bufH[N,128] fp16
    k_agg64h<<<aggBlocks, 256>>>(bufH, bufHA);
    k_gemm<64, 128, 8, true, false, true, true, true, 0><<<gemmBlocks, 256>>>(
        bufHA, W1, b1, bufH, NNODES);
    k_bnfin<<<1, 128>>>(ga1, be1, 0);

    // layer 2: agg(relu(BN1(h1))) -> bufHA[N,128] fp16; GEMM2 -> bufB[N,128] fp32
    k_agg128h_bn<<<aggBlocks, 256>>>(bufH, bufHA);
    k_gemm<128, 128, 8, true, false, true, true, false, 256><<<gemmBlocks, 256>>>(
        bufHA, W2, b2, bufB, NNODES);
    k_bnfin<<<1, 128>>>(ga2, be2, 256);

    // layer 3: t = relu(BN2(h2)) @ W3^T -> bufH[N,64] fp16; agg(t)+b3 -> out
    k_gemm<128, 64, 4, false, true, false, false, true, 0><<<gemmBlocks, 256>>>(
        bufB, W3, nullptr, bufH, NNODES);
    k_agg64h_bias<<<aggBlocks, 256>>>(bufH, b3, out);
}